// round 10
// baseline (speedup 1.0000x reference)
#include <cuda_runtime.h>
#include <math.h>
#include <stdint.h>

#define B_  4
#define S_  2048
#define D_  512
#define H_  8
#define HD_ 64
#define NR  (B_ * S_)   // 8192 rows

// Scratch buffers (no allocation allowed in kernel_launch).
__device__ __align__(16) float g_fused[NR * D_];
__device__ __align__(16) float g_Q[NR * D_];
__device__ __align__(16) float g_K[NR * D_];
__device__ __align__(16) float g_V[NR * D_];
__device__ __align__(16) float g_att[NR * D_];
// Pre-rounded (tf32) operand copies.
__device__ __align__(16) float g_gene_r[NR * D_];
__device__ __align__(16) float g_expr_r[NR * D_];
__device__ __align__(16) float g_Wf_r[2 * D_ * D_];
__device__ __align__(16) float g_Wq_r[D_ * D_];
__device__ __align__(16) float g_Wk_r[D_ * D_];
__device__ __align__(16) float g_Wv_r[D_ * D_];
__device__ __align__(16) float g_Wo_r[D_ * D_];

// ---------------------------------------------------------------------------
// TF32 / cp.async helpers
// ---------------------------------------------------------------------------
__device__ __forceinline__ uint32_t f2tf(float x) {
    uint32_t u;
    asm("cvt.rna.tf32.f32 %0, %1;" : "=r"(u) : "f"(x));
    return u;
}
__device__ __forceinline__ float f2tff(float x) {
    return __uint_as_float(f2tf(x));
}
// D(16x8,f32) += A(16x8,tf32,row) * B(8x8,tf32,col)
__device__ __forceinline__ void mma8(float* d, const uint32_t* a, const uint32_t* b) {
    asm volatile(
        "mma.sync.aligned.m16n8k8.row.col.f32.tf32.tf32.f32 "
        "{%0,%1,%2,%3}, {%4,%5,%6,%7}, {%8,%9}, {%0,%1,%2,%3};"
        : "+f"(d[0]), "+f"(d[1]), "+f"(d[2]), "+f"(d[3])
        : "r"(a[0]), "r"(a[1]), "r"(a[2]), "r"(a[3]), "r"(b[0]), "r"(b[1]));
}
__device__ __forceinline__ void cp16(void* smem_dst, const void* gsrc) {
    uint32_t s = (uint32_t)__cvta_generic_to_shared(smem_dst);
    asm volatile("cp.async.cg.shared.global [%0], [%1], 16;" :: "r"(s), "l"(gsrc));
}
#define CP_COMMIT() asm volatile("cp.async.commit_group;")
#define CP_WAIT(n)  asm volatile("cp.async.wait_group %0;" :: "n"(n))

// ---------------------------------------------------------------------------
// Elementwise tf32 pre-round (cvt.rna), float4-vectorized.
// ---------------------------------------------------------------------------
__global__ void round_tf32_kernel(const float* __restrict__ in,
                                  float* __restrict__ out, int n4)
{
    int i = blockIdx.x * blockDim.x + threadIdx.x;
    if (i < n4) {
        float4 v = ((const float4*)in)[i];
        ((float4*)out)[i] =
            make_float4(f2tff(v.x), f2tff(v.y), f2tff(v.z), f2tff(v.w));
    }
}

// ---------------------------------------------------------------------------
// TF32 tensor-core GEMM: C[M,512] = A[M,K] @ Bw[K,512] + bias.
// ALL operands pre-rounded to tf32 in gmem -> tiles move raw via cp.async,
// 4-stage ring (3 in flight), zero staging registers, one sync per k-iter.
// round_out=1: store outputs pre-rounded (cvt.rna) for downstream raw loads.
// Concat: logical A row = A[0..KA) ++ A2[0..K-KA); k-tiles never straddle KA.
// CTA 128x128, 256 threads, 8 warps (2m x 4n), warp tile 64x32.
// ---------------------------------------------------------------------------
#define GSTAGES 4
#define GA_ELEM (128 * 20)
#define GB_ELEM (16 * 132)
#define GEMM_SMEM (GSTAGES * (GA_ELEM + GB_ELEM) * 4)   // 74752 B

__global__ __launch_bounds__(256, 2) void gemm_tf32(
    const float* __restrict__ A, const float* __restrict__ A2, int KA,
    const float* __restrict__ Bw, const float* __restrict__ bias,
    float* __restrict__ C, int K, int round_out)
{
    extern __shared__ float gsm[];
    float* AsB = gsm;                          // [GSTAGES][128][20]
    float* BsB = gsm + GSTAGES * GA_ELEM;      // [GSTAGES][16][132]

    const int tid  = threadIdx.x;
    const int lane = tid & 31, wid = tid >> 5;
    const int g = lane >> 2, t = lane & 3;
    const int wm = (wid >> 2) * 64;
    const int wn = (wid & 3) * 32;
    const int row0 = blockIdx.y * 128;
    const int col0 = blockIdx.x * 128;

    const int ar = tid >> 1;            // 0..127
    const int ac = (tid & 1) * 8;       // 0 or 8
    const int bk = tid >> 4;            // 0..15
    const int bc = (tid & 15) * 8;      // 0..120

    float acc[4][4][4];
    #pragma unroll
    for (int i = 0; i < 4; i++)
        #pragma unroll
        for (int j = 0; j < 4; j++)
            #pragma unroll
            for (int v = 0; v < 4; v++) acc[i][j][v] = 0.0f;

    const int niter = K >> 4;

    auto issue = [&](int it) {
        const int s = it & (GSTAGES - 1);
        const int k0 = it << 4;
        const float* src = (k0 < KA) ? A : A2;
        const int koff = (k0 < KA) ? k0 : k0 - KA;
        const float* p = &src[(size_t)(row0 + ar) * KA + koff + ac];
        float* as = AsB + s * GA_ELEM + ar * 20 + ac;
        cp16(as, p);
        cp16(as + 4, p + 4);
        const float* q = &Bw[(size_t)(k0 + bk) * D_ + col0 + bc];
        float* bs = BsB + s * GB_ELEM + bk * 132 + bc;
        cp16(bs, q);
        cp16(bs + 4, q + 4);
        CP_COMMIT();
    };

    issue(0); issue(1); issue(2);

    for (int it = 0; it < niter; it++) {
        const int cur = it & (GSTAGES - 1);
        CP_WAIT(2);          // tile `it` arrived (<=2 younger groups pending)
        __syncthreads();     // slot (it+3)%4 free: last read at iter it-1
        if (it + 3 < niter) issue(it + 3);
        else CP_COMMIT();    // keep group accounting aligned

        const uint32_t* Au = (const uint32_t*)(AsB + cur * GA_ELEM);
        const uint32_t* Bu = (const uint32_t*)(BsB + cur * GB_ELEM);
        #pragma unroll
        for (int ks = 0; ks < 2; ks++) {
            const int kk = ks * 8;
            uint32_t a[4][4];
            #pragma unroll
            for (int mt = 0; mt < 4; mt++) {
                int m = wm + mt * 16;
                a[mt][0] = Au[(m + g) * 20 + kk + t];
                a[mt][1] = Au[(m + g + 8) * 20 + kk + t];
                a[mt][2] = Au[(m + g) * 20 + kk + t + 4];
                a[mt][3] = Au[(m + g + 8) * 20 + kk + t + 4];
            }
            #pragma unroll
            for (int nt = 0; nt < 4; nt++) {
                int n = wn + nt * 8 + g;
                uint32_t bf[2] = { Bu[(kk + t) * 132 + n], Bu[(kk + t + 4) * 132 + n] };
                #pragma unroll
                for (int mt = 0; mt < 4; mt++) mma8(acc[mt][nt], a[mt], bf);
            }
        }
    }

    // epilogue: bias + store (c0,c1 adjacent cols -> float2)
    #pragma unroll
    for (int mt = 0; mt < 4; mt++) {
        int r = row0 + wm + mt * 16 + g;
        #pragma unroll
        for (int nt = 0; nt < 4; nt++) {
            int c = col0 + wn + nt * 8 + 2 * t;
            float b0v = bias[c], b1v = bias[c + 1];
            float o0 = acc[mt][nt][0] + b0v, o1 = acc[mt][nt][1] + b1v;
            float o2 = acc[mt][nt][2] + b0v, o3 = acc[mt][nt][3] + b1v;
            if (round_out) {
                o0 = f2tff(o0); o1 = f2tff(o1); o2 = f2tff(o2); o3 = f2tff(o3);
            }
            *(float2*)&C[(size_t)r * D_ + c]       = make_float2(o0, o1);
            *(float2*)&C[(size_t)(r + 8) * D_ + c] = make_float2(o2, o3);
        }
    }
}

// ---------------------------------------------------------------------------
// TF32 fused masked-softmax attention (flash-style, NO online max).
// Scores are bounded (|s| ~ <10: unit-variance Q/K, HD=64, scale .125, M in
// [0,1]) so exp2 cannot overflow, and the max-shift cancels exactly in
//   A_bar = p*M / (Zm + EPS*Zs),  p = exp2(CL*M*(Q.K)),  Zs=sum p, Zm=sum p*M.
// CTA: 128 q rows, 256 threads (8 warps x 16q). 32 key blocks of 64.
// Q/K/V arrive PRE-ROUNDED tf32 -> raw cp.async tile movement. Q fragments in
// registers; P scratch aliases the dead Q smem region. K/V double-buffered,
// next tile's cp.async issued right after the score MMAs, one sync per iter.
// M read directly from gmem (L2-resident) in the C-fragment pattern.
// ---------------------------------------------------------------------------
#define AT_STRIDE 68
#define ATTN_SMEM ((128 * AT_STRIDE + 4 * 64 * AT_STRIDE) * 4)   // 104448 B

__global__ __launch_bounds__(256, 2) void attn_tf32(
    const float* __restrict__ Qg, const float* __restrict__ Kg,
    const float* __restrict__ Vg, const float* __restrict__ Mg,
    float* __restrict__ Og)
{
    extern __shared__ float sm[];
    float* Qs = sm;                            // [128][68] (q x d) -> later P scratch
    float* Ks = sm + 128 * AT_STRIDE;          // [2][64][68] (k x d)
    float* Vs = Ks + 2 * 64 * AT_STRIDE;       // [2][64][68] (k x d)
    float* Ps = sm;                            // aliases Qs (per-warp 16 rows)

    const int tid  = threadIdx.x;
    const int lane = tid & 31, w = tid >> 5;
    const int g = lane >> 2, t = lane & 3;
    const int qw = w * 16;
    const int b = blockIdx.z, h = blockIdx.y, qb = blockIdx.x;

    const float CL = 0.125f * 1.4426950408889634f;   // scale * log2e

    const float* Qbase = Qg + ((size_t)(b * S_ + qb * 128)) * D_ + h * HD_;
    const float* Kbase = Kg + ((size_t)(b * S_)) * D_ + h * HD_;
    const float* Vbase = Vg + ((size_t)(b * S_)) * D_ + h * HD_;
    const float* Mrow0 = Mg + (size_t)b * S_ * S_ + (size_t)(qb * 128 + qw + g) * S_;
    const float* Mrow1 = Mrow0 + (size_t)8 * S_;
    float*       Obase = Og + ((size_t)(b * S_ + qb * 128)) * D_ + h * HD_;

    const int ldr = tid >> 4;              // cooperative-load row base (0..15)
    const int ldc = (tid & 15) * 4;        // cooperative-load col

    // ---- prologue: cp.async Q (group A), then K/V tile 0 (group B) ----
    #pragma unroll
    for (int itl = 0; itl < 8; itl++) {
        int r = ldr + itl * 16;
        cp16(&Qs[r * AT_STRIDE + ldc], &Qbase[(size_t)r * D_ + ldc]);
    }
    CP_COMMIT();
    #pragma unroll
    for (int itl = 0; itl < 4; itl++) {
        int r = ldr + itl * 16;
        cp16(&Ks[r * AT_STRIDE + ldc], &Kbase[(size_t)r * D_ + ldc]);
        cp16(&Vs[r * AT_STRIDE + ldc], &Vbase[(size_t)r * D_ + ldc]);
    }
    CP_COMMIT();

    CP_WAIT(1);          // Q arrived (K/V tile 0 may still be in flight)
    __syncthreads();

    // ---- Q fragments -> registers (loop-invariant) ----
    uint32_t qa[8][4];
    {
        const uint32_t* Qu = (const uint32_t*)Qs;
        #pragma unroll
        for (int ks = 0; ks < 8; ks++) {
            qa[ks][0] = Qu[(qw + g) * AT_STRIDE + ks * 8 + t];
            qa[ks][1] = Qu[(qw + g + 8) * AT_STRIDE + ks * 8 + t];
            qa[ks][2] = Qu[(qw + g) * AT_STRIDE + ks * 8 + t + 4];
            qa[ks][3] = Qu[(qw + g + 8) * AT_STRIDE + ks * 8 + t + 4];
        }
    }

    float acc[8][4];
    #pragma unroll
    for (int i = 0; i < 8; i++)
        #pragma unroll
        for (int v = 0; v < 4; v++) acc[i][v] = 0.0f;
    float Zs0 = 0.f, Zs1 = 0.f, Zm0 = 0.f, Zm1 = 0.f;

    for (int kb = 0; kb < S_ / 64; kb++) {
        const int cur = kb & 1;
        const bool has_next = (kb + 1 < S_ / 64);
        const float* Kscur = Ks + cur * 64 * AT_STRIDE;
        const float* Vscur = Vs + cur * 64 * AT_STRIDE;

        CP_WAIT(0);        // tile kb fully arrived
        __syncthreads();   // all warps see it; buf^1 reads from iter kb-1 done

        // --- scores: S[16q,64k] = Q @ K^T (warp) ---
        const uint32_t* Ku = (const uint32_t*)Kscur;
        float sc[8][4];
        #pragma unroll
        for (int nt = 0; nt < 8; nt++)
            #pragma unroll
            for (int v = 0; v < 4; v++) sc[nt][v] = 0.0f;

        #pragma unroll
        for (int ks = 0; ks < 8; ks++) {
            #pragma unroll
            for (int nt = 0; nt < 8; nt++) {
                uint32_t bf[2] = { Ku[(nt * 8 + g) * AT_STRIDE + ks * 8 + t],
                                   Ku[(nt * 8 + g) * AT_STRIDE + ks * 8 + t + 4] };
                mma8(sc[nt], qa[ks], bf);
            }
        }

        // --- issue cp.async for tile kb+1 into the other buffer ---
        if (has_next) {
            float* Ksn = Ks + (cur ^ 1) * 64 * AT_STRIDE;
            float* Vsn = Vs + (cur ^ 1) * 64 * AT_STRIDE;
            #pragma unroll
            for (int itl = 0; itl < 4; itl++) {
                int r = ldr + itl * 16;
                cp16(&Ksn[r * AT_STRIDE + ldc],
                     &Kbase[(size_t)((kb + 1) * 64 + r) * D_ + ldc]);
                cp16(&Vsn[r * AT_STRIDE + ldc],
                     &Vbase[(size_t)((kb + 1) * 64 + r) * D_ + ldc]);
            }
            CP_COMMIT();
        }

        // --- single pass: mask*scale, exp2, Z sums, P (= p*M) to smem tf32 ---
        const float* Mc0 = Mrow0 + kb * 64;
        const float* Mc1 = Mrow1 + kb * 64;
        float* Pw = Ps + w * 16 * AT_STRIDE;
        #pragma unroll
        for (int nt = 0; nt < 8; nt++) {
            float2 mA = *(const float2*)&Mc0[nt * 8 + 2 * t];
            float2 mB = *(const float2*)&Mc1[nt * 8 + 2 * t];
            float p0 = exp2f(sc[nt][0] * (CL * mA.x));
            float p1 = exp2f(sc[nt][1] * (CL * mA.y));
            float p2 = exp2f(sc[nt][2] * (CL * mB.x));
            float p3 = exp2f(sc[nt][3] * (CL * mB.y));
            Zs0 += p0 + p1; Zs1 += p2 + p3;
            p0 *= mA.x; p1 *= mA.y; p2 *= mB.x; p3 *= mB.y;
            Zm0 += p0 + p1; Zm1 += p2 + p3;
            *(float2*)&Pw[g * AT_STRIDE + nt * 8 + 2 * t] =
                make_float2(f2tff(p0), f2tff(p1));
            *(float2*)&Pw[(g + 8) * AT_STRIDE + nt * 8 + 2 * t] =
                make_float2(f2tff(p2), f2tff(p3));
        }
        __syncwarp();   // order P stores before P fragment loads (same warp)

        // --- out += P[16q,64k] @ V[64k,64d] ---
        const uint32_t* Pu = (const uint32_t*)Pw;
        const uint32_t* Vu = (const uint32_t*)Vscur;
        #pragma unroll
        for (int ks = 0; ks < 8; ks++) {
            uint32_t a[4];
            a[0] = Pu[g * AT_STRIDE + ks * 8 + t];
            a[1] = Pu[(g + 8) * AT_STRIDE + ks * 8 + t];
            a[2] = Pu[g * AT_STRIDE + ks * 8 + t + 4];
            a[3] = Pu[(g + 8) * AT_STRIDE + ks * 8 + t + 4];
            #pragma unroll
            for (int dt = 0; dt < 8; dt++) {
                uint32_t bf[2] = { Vu[(ks * 8 + t) * AT_STRIDE + dt * 8 + g],
                                   Vu[(ks * 8 + t + 4) * AT_STRIDE + dt * 8 + g] };
                mma8(acc[dt], a, bf);
            }
        }
    }

    // final: reduce Z over quad lanes, normalize, store (pre-rounded tf32:
    // att feeds the O-GEMM's raw cp.async A loads).
    Zs0 += __shfl_xor_sync(0xffffffffu, Zs0, 1);
    Zs0 += __shfl_xor_sync(0xffffffffu, Zs0, 2);
    Zs1 += __shfl_xor_sync(0xffffffffu, Zs1, 1);
    Zs1 += __shfl_xor_sync(0xffffffffu, Zs1, 2);
    Zm0 += __shfl_xor_sync(0xffffffffu, Zm0, 1);
    Zm0 += __shfl_xor_sync(0xffffffffu, Zm0, 2);
    Zm1 += __shfl_xor_sync(0xffffffffu, Zm1, 1);
    Zm1 += __shfl_xor_sync(0xffffffffu, Zm1, 2);
    float inv0 = 1.0f / (Zm0 + 1e-8f * Zs0);
    float inv1 = 1.0f / (Zm1 + 1e-8f * Zs1);

    #pragma unroll
    for (int dt = 0; dt < 8; dt++) {
        int c = dt * 8 + 2 * t;
        *(float2*)&Obase[(size_t)(qw + g) * D_ + c] =
            make_float2(f2tff(acc[dt][0] * inv0), f2tff(acc[dt][1] * inv0));
        *(float2*)&Obase[(size_t)(qw + g + 8) * D_ + c] =
            make_float2(f2tff(acc[dt][2] * inv1), f2tff(acc[dt][3] * inv1));
    }
}

// ---------------------------------------------------------------------------
extern "C" void kernel_launch(void* const* d_in, const int* in_sizes, int n_in,
                              void* d_out, int out_size)
{
    const float* gene    = (const float*)d_in[0];
    const float* expr    = (const float*)d_in[1];
    const float* Mm      = (const float*)d_in[2];
    const float* W_fused = (const float*)d_in[3];
    const float* b_fused = (const float*)d_in[4];
    const float* W_Q     = (const float*)d_in[5];
    const float* b_Q     = (const float*)d_in[6];
    const float* W_K     = (const float*)d_in[7];
    const float* b_K     = (const float*)d_in[8];
    const float* W_V     = (const float*)d_in[9];
    const float* b_V     = (const float*)d_in[10];
    const float* W_O     = (const float*)d_in[11];
    const float* b_O     = (const float*)d_in[12];
    float* out = (float*)d_out;

    float *fusedp, *Qp, *Kp, *Vp, *attp;
    float *gener, *exprr, *wfr, *wqr, *wkr, *wvr, *wor;
    cudaGetSymbolAddress((void**)&fusedp, g_fused);
    cudaGetSymbolAddress((void**)&Qp, g_Q);
    cudaGetSymbolAddress((void**)&Kp, g_K);
    cudaGetSymbolAddress((void**)&Vp, g_V);
    cudaGetSymbolAddress((void**)&attp, g_att);
    cudaGetSymbolAddress((void**)&gener, g_gene_r);
    cudaGetSymbolAddress((void**)&exprr, g_expr_r);
    cudaGetSymbolAddress((void**)&wfr, g_Wf_r);
    cudaGetSymbolAddress((void**)&wqr, g_Wq_r);
    cudaGetSymbolAddress((void**)&wkr, g_Wk_r);
    cudaGetSymbolAddress((void**)&wvr, g_Wv_r);
    cudaGetSymbolAddress((void**)&wor, g_Wo_r);

    cudaFuncSetAttribute(gemm_tf32,
                         cudaFuncAttributeMaxDynamicSharedMemorySize, GEMM_SMEM);
    cudaFuncSetAttribute(attn_tf32,
                         cudaFuncAttributeMaxDynamicSharedMemorySize, ATTN_SMEM);

    // Pre-round all mma operands to tf32 (cvt.rna; idempotent downstream).
    auto rnd = [](const float* in, float* outp, int n) {
        int n4 = n / 4;
        round_tf32_kernel<<<(n4 + 255) / 256, 256>>>(in, outp, n4);
    };
    rnd(gene,    gener, NR * D_);
    rnd(expr,    exprr, NR * D_);
    rnd(W_fused, wfr,   2 * D_ * D_);
    rnd(W_Q,     wqr,   D_ * D_);
    rnd(W_K,     wkr,   D_ * D_);
    rnd(W_V,     wvr,   D_ * D_);
    rnd(W_O,     wor,   D_ * D_);

    dim3 gg(D_ / 128, NR / 128);   // (4, 64)

    gemm_tf32<<<gg, 256, GEMM_SMEM>>>(gener, exprr, 512, wfr, b_fused, fusedp, 1024, 1);
    gemm_tf32<<<gg, 256, GEMM_SMEM>>>(fusedp, fusedp, 512, wqr, b_Q, Qp, 512, 1);
    gemm_tf32<<<gg, 256, GEMM_SMEM>>>(fusedp, fusedp, 512, wkr, b_K, Kp, 512, 1);
    gemm_tf32<<<gg, 256, GEMM_SMEM>>>(exprr,  exprr,  512, wvr, b_V, Vp, 512, 1);
    attn_tf32<<<dim3(S_ / 128, H_, B_), 256, ATTN_SMEM>>>(Qp, Kp, Vp, Mm, attp);
    gemm_tf32<<<gg, 256, GEMM_SMEM>>>(attp, attp, 512, wor, b_O, out, 512, 0);
}

// round 11
// speedup vs baseline: 1.4770x; 1.4770x over previous
#include <cuda_runtime.h>
#include <math.h>
#include <stdint.h>

#define B_  4
#define S_  2048
#define D_  512
#define H_  8
#define HD_ 64
#define NR  (B_ * S_)   // 8192 rows

// Scratch buffers (no allocation allowed in kernel_launch).
__device__ __align__(16) float g_fused[NR * D_];
__device__ __align__(16) float g_Q[NR * D_];
__device__ __align__(16) float g_K[NR * D_];
__device__ __align__(16) float g_V[NR * D_];
__device__ __align__(16) float g_att[NR * D_];

// ---------------------------------------------------------------------------
// TF32 / cp.async helpers
// ---------------------------------------------------------------------------
__device__ __forceinline__ uint32_t f2tf(float x) {
    uint32_t u;
    asm("cvt.rna.tf32.f32 %0, %1;" : "=r"(u) : "f"(x));
    return u;
}
__device__ __forceinline__ float f2tff(float x) {
    return __uint_as_float(f2tf(x));
}
// D(16x8,f32) += A(16x8,tf32,row) * B(8x8,tf32,col)
__device__ __forceinline__ void mma8(float* d, const uint32_t* a, const uint32_t* b) {
    asm volatile(
        "mma.sync.aligned.m16n8k8.row.col.f32.tf32.tf32.f32 "
        "{%0,%1,%2,%3}, {%4,%5,%6,%7}, {%8,%9}, {%0,%1,%2,%3};"
        : "+f"(d[0]), "+f"(d[1]), "+f"(d[2]), "+f"(d[3])
        : "r"(a[0]), "r"(a[1]), "r"(a[2]), "r"(a[3]), "r"(b[0]), "r"(b[1]));
}
__device__ __forceinline__ void cp16(void* smem_dst, const void* gsrc) {
    uint32_t s = (uint32_t)__cvta_generic_to_shared(smem_dst);
    asm volatile("cp.async.cg.shared.global [%0], [%1], 16;" :: "r"(s), "l"(gsrc));
}
#define CP_COMMIT() asm volatile("cp.async.commit_group;")
#define CP_WAIT(n)  asm volatile("cp.async.wait_group %0;" :: "n"(n))

// ---------------------------------------------------------------------------
// TF32 tensor-core GEMM: C[M,512] = A[M,K] @ Bw[K,512] + bias.
// Double-buffered smem: one __syncthreads per k-iter, LDG prefetch overlaps mma.
// round_out=1: store outputs pre-rounded to tf32 (cvt.rna). Consumers that
// would re-apply cvt.rna on load see bit-identical values (idempotent).
// CTA 128x128, 256 threads, 8 warps (2m x 4n), warp tile 64x32.
// ---------------------------------------------------------------------------
__global__ __launch_bounds__(256, 2) void gemm_tf32(
    const float* __restrict__ A, const float* __restrict__ A2, int KA,
    const float* __restrict__ Bw, const float* __restrict__ bias,
    float* __restrict__ C, int K, int round_out)
{
    __shared__ float As[2][128][20];   // [m][k], pad: frag LDS conflict-free
    __shared__ float Bs[2][16][132];   // [k][n]

    const int tid  = threadIdx.x;
    const int lane = tid & 31, wid = tid >> 5;
    const int g = lane >> 2, t = lane & 3;
    const int wm = (wid >> 2) * 64;
    const int wn = (wid & 3) * 32;
    const int row0 = blockIdx.y * 128;
    const int col0 = blockIdx.x * 128;

    const int ar = tid >> 1;            // 0..127
    const int ac = (tid & 1) * 8;       // 0 or 8
    const int bk = tid >> 4;            // 0..15
    const int bc = (tid & 15) * 8;      // 0..120

    float acc[4][4][4];
    #pragma unroll
    for (int i = 0; i < 4; i++)
        #pragma unroll
        for (int j = 0; j < 4; j++)
            #pragma unroll
            for (int v = 0; v < 4; v++) acc[i][j][v] = 0.0f;

    const int niter = K >> 4;
    float4 pa0, pa1, pb0, pb1;

    auto prefetch = [&](int it) {
        int k0 = it << 4;
        const float* src = (k0 < KA) ? A : A2;
        int koff = (k0 < KA) ? k0 : k0 - KA;
        const float* p = &src[(size_t)(row0 + ar) * KA + koff + ac];
        pa0 = *(const float4*)p; pa1 = *(const float4*)(p + 4);
        const float* q = &Bw[(size_t)(k0 + bk) * D_ + col0 + bc];
        pb0 = *(const float4*)q; pb1 = *(const float4*)(q + 4);
    };
    auto stage = [&](int buf) {
        *(float4*)&As[buf][ar][ac]     = make_float4(f2tff(pa0.x), f2tff(pa0.y), f2tff(pa0.z), f2tff(pa0.w));
        *(float4*)&As[buf][ar][ac + 4] = make_float4(f2tff(pa1.x), f2tff(pa1.y), f2tff(pa1.z), f2tff(pa1.w));
        *(float4*)&Bs[buf][bk][bc]     = make_float4(f2tff(pb0.x), f2tff(pb0.y), f2tff(pb0.z), f2tff(pb0.w));
        *(float4*)&Bs[buf][bk][bc + 4] = make_float4(f2tff(pb1.x), f2tff(pb1.y), f2tff(pb1.z), f2tff(pb1.w));
    };

    prefetch(0);
    stage(0);
    __syncthreads();

    for (int it = 0; it < niter; it++) {
        const int cur = it & 1;
        if (it + 1 < niter) prefetch(it + 1);

        const uint32_t* Au = (const uint32_t*)As[cur];
        const uint32_t* Bu = (const uint32_t*)Bs[cur];
        #pragma unroll
        for (int ks = 0; ks < 2; ks++) {
            const int kk = ks * 8;
            uint32_t a[4][4];
            #pragma unroll
            for (int mt = 0; mt < 4; mt++) {
                int m = wm + mt * 16;
                a[mt][0] = Au[(m + g) * 20 + kk + t];
                a[mt][1] = Au[(m + g + 8) * 20 + kk + t];
                a[mt][2] = Au[(m + g) * 20 + kk + t + 4];
                a[mt][3] = Au[(m + g + 8) * 20 + kk + t + 4];
            }
            #pragma unroll
            for (int nt = 0; nt < 4; nt++) {
                int n = wn + nt * 8 + g;
                uint32_t bf[2] = { Bu[(kk + t) * 132 + n], Bu[(kk + t + 4) * 132 + n] };
                #pragma unroll
                for (int mt = 0; mt < 4; mt++) mma8(acc[mt][nt], a[mt], bf);
            }
        }

        if (it + 1 < niter) {
            stage(cur ^ 1);
            __syncthreads();
        }
    }

    // epilogue: bias + store (c0,c1 adjacent cols -> float2)
    #pragma unroll
    for (int mt = 0; mt < 4; mt++) {
        int r = row0 + wm + mt * 16 + g;
        #pragma unroll
        for (int nt = 0; nt < 4; nt++) {
            int c = col0 + wn + nt * 8 + 2 * t;
            float b0v = bias[c], b1v = bias[c + 1];
            float o0 = acc[mt][nt][0] + b0v, o1 = acc[mt][nt][1] + b1v;
            float o2 = acc[mt][nt][2] + b0v, o3 = acc[mt][nt][3] + b1v;
            if (round_out) {
                o0 = f2tff(o0); o1 = f2tff(o1); o2 = f2tff(o2); o3 = f2tff(o3);
            }
            *(float2*)&C[(size_t)r * D_ + c]       = make_float2(o0, o1);
            *(float2*)&C[(size_t)(r + 8) * D_ + c] = make_float2(o2, o3);
        }
    }
}

// ---------------------------------------------------------------------------
// TF32 fused masked-softmax attention (flash-style, NO online max).
// Scores are bounded (unit-variance Q/K, HD=64, scale .125, M in [0,1]) so
// exp2 cannot overflow, and a max-shift cancels exactly in
//   A_bar = p*M / (Zm + EPS*Zs),  p = exp2(CL*M*(Q.K)),  Zs=sum p, Zm=sum p*M.
// CTA: 128 q rows, 256 threads (8 warps x 16q). 32 key blocks of 64.
// Q/K/V arrive PRE-ROUNDED to tf32 (producer GEMM round_out=1), so all tile
// movement is raw cp.async gmem->smem: zero staging registers, bit-identical
// numerics vs converting on load. Q fragments live in registers; P scratch
// aliases the dead Q smem region (warp-private rows). K/V double-buffered:
// next tile's cp.async issues after this iter's sync (buf^1 provably idle),
// overlapping the softmax+PV phases. One __syncthreads per iteration.
// M is read directly from gmem (L2-resident) in the C-fragment pattern.
// ---------------------------------------------------------------------------
#define AT_STRIDE 68
#define ATTN_SMEM ((128 * AT_STRIDE + 4 * 64 * AT_STRIDE) * 4)   // 104448 B

__global__ __launch_bounds__(256, 2) void attn_tf32(
    const float* __restrict__ Qg, const float* __restrict__ Kg,
    const float* __restrict__ Vg, const float* __restrict__ Mg,
    float* __restrict__ Og)
{
    extern __shared__ float sm[];
    float* Qs = sm;                            // [128][68] (q x d) -> later P scratch
    float* Ks = sm + 128 * AT_STRIDE;          // [2][64][68] (k x d)
    float* Vs = Ks + 2 * 64 * AT_STRIDE;       // [2][64][68] (k x d)
    float* Ps = sm;                            // aliases Qs (per-warp 16 rows)

    const int tid  = threadIdx.x;
    const int lane = tid & 31, w = tid >> 5;
    const int g = lane >> 2, t = lane & 3;
    const int qw = w * 16;
    const int b = blockIdx.z, h = blockIdx.y, qb = blockIdx.x;

    const float CL = 0.125f * 1.4426950408889634f;   // scale * log2e

    const float* Qbase = Qg + ((size_t)(b * S_ + qb * 128)) * D_ + h * HD_;
    const float* Kbase = Kg + ((size_t)(b * S_)) * D_ + h * HD_;
    const float* Vbase = Vg + ((size_t)(b * S_)) * D_ + h * HD_;
    const float* Mrow0 = Mg + (size_t)b * S_ * S_ + (size_t)(qb * 128 + qw + g) * S_;
    const float* Mrow1 = Mrow0 + (size_t)8 * S_;
    float*       Obase = Og + ((size_t)(b * S_ + qb * 128)) * D_ + h * HD_;

    const int ldr = tid >> 4;              // cooperative-load row base (0..15)
    const int ldc = (tid & 15) * 4;        // cooperative-load col

    // ---- prologue: cp.async Q (group A), then K/V tile 0 (group B) ----
    #pragma unroll
    for (int itl = 0; itl < 8; itl++) {
        int r = ldr + itl * 16;
        cp16(&Qs[r * AT_STRIDE + ldc], &Qbase[(size_t)r * D_ + ldc]);
    }
    CP_COMMIT();
    #pragma unroll
    for (int itl = 0; itl < 4; itl++) {
        int r = ldr + itl * 16;
        cp16(&Ks[r * AT_STRIDE + ldc], &Kbase[(size_t)r * D_ + ldc]);
        cp16(&Vs[r * AT_STRIDE + ldc], &Vbase[(size_t)r * D_ + ldc]);
    }
    CP_COMMIT();

    CP_WAIT(1);          // Q arrived (K/V tile 0 may still be in flight)
    __syncthreads();

    // ---- Q fragments -> registers (loop-invariant) ----
    uint32_t qa[8][4];
    {
        const uint32_t* Qu = (const uint32_t*)Qs;
        #pragma unroll
        for (int ks = 0; ks < 8; ks++) {
            qa[ks][0] = Qu[(qw + g) * AT_STRIDE + ks * 8 + t];
            qa[ks][1] = Qu[(qw + g + 8) * AT_STRIDE + ks * 8 + t];
            qa[ks][2] = Qu[(qw + g) * AT_STRIDE + ks * 8 + t + 4];
            qa[ks][3] = Qu[(qw + g + 8) * AT_STRIDE + ks * 8 + t + 4];
        }
    }

    float acc[8][4];
    #pragma unroll
    for (int i = 0; i < 8; i++)
        #pragma unroll
        for (int v = 0; v < 4; v++) acc[i][v] = 0.0f;
    float Zs0 = 0.f, Zs1 = 0.f, Zm0 = 0.f, Zm1 = 0.f;

    for (int kb = 0; kb < S_ / 64; kb++) {
        const int cur = kb & 1;
        const bool has_next = (kb + 1 < S_ / 64);
        const float* Kscur = Ks + cur * 64 * AT_STRIDE;
        const float* Vscur = Vs + cur * 64 * AT_STRIDE;

        CP_WAIT(0);        // tile kb fully arrived
        __syncthreads();   // all warps see it; buf^1 reads from iter kb-1 done

        // --- scores: S[16q,64k] = Q @ K^T (warp) ---
        const uint32_t* Ku = (const uint32_t*)Kscur;
        float sc[8][4];
        #pragma unroll
        for (int nt = 0; nt < 8; nt++)
            #pragma unroll
            for (int v = 0; v < 4; v++) sc[nt][v] = 0.0f;

        #pragma unroll
        for (int ks = 0; ks < 8; ks++) {
            #pragma unroll
            for (int nt = 0; nt < 8; nt++) {
                uint32_t bf[2] = { Ku[(nt * 8 + g) * AT_STRIDE + ks * 8 + t],
                                   Ku[(nt * 8 + g) * AT_STRIDE + ks * 8 + t + 4] };
                mma8(sc[nt], qa[ks], bf);
            }
        }

        // --- issue cp.async for tile kb+1 into the other buffer ---
        // Safe: every thread passed this iter's __syncthreads, so no thread
        // still reads buf^1 (last read at iter kb-1). Copy overlaps softmax+PV.
        if (has_next) {
            float* Ksn = Ks + (cur ^ 1) * 64 * AT_STRIDE;
            float* Vsn = Vs + (cur ^ 1) * 64 * AT_STRIDE;
            #pragma unroll
            for (int itl = 0; itl < 4; itl++) {
                int r = ldr + itl * 16;
                cp16(&Ksn[r * AT_STRIDE + ldc],
                     &Kbase[(size_t)((kb + 1) * 64 + r) * D_ + ldc]);
                cp16(&Vsn[r * AT_STRIDE + ldc],
                     &Vbase[(size_t)((kb + 1) * 64 + r) * D_ + ldc]);
            }
            CP_COMMIT();
        }

        // --- single pass: mask*scale, exp2, Z sums, P (= p*M) to smem tf32 ---
        const float* Mc0 = Mrow0 + kb * 64;
        const float* Mc1 = Mrow1 + kb * 64;
        float* Pw = Ps + w * 16 * AT_STRIDE;
        #pragma unroll
        for (int nt = 0; nt < 8; nt++) {
            float2 mA = *(const float2*)&Mc0[nt * 8 + 2 * t];
            float2 mB = *(const float2*)&Mc1[nt * 8 + 2 * t];
            float p0 = exp2f(sc[nt][0] * (CL * mA.x));
            float p1 = exp2f(sc[nt][1] * (CL * mA.y));
            float p2 = exp2f(sc[nt][2] * (CL * mB.x));
            float p3 = exp2f(sc[nt][3] * (CL * mB.y));
            Zs0 += p0 + p1; Zs1 += p2 + p3;
            p0 *= mA.x; p1 *= mA.y; p2 *= mB.x; p3 *= mB.y;
            Zm0 += p0 + p1; Zm1 += p2 + p3;
            *(float2*)&Pw[g * AT_STRIDE + nt * 8 + 2 * t] =
                make_float2(f2tff(p0), f2tff(p1));
            *(float2*)&Pw[(g + 8) * AT_STRIDE + nt * 8 + 2 * t] =
                make_float2(f2tff(p2), f2tff(p3));
        }
        __syncwarp();   // order P stores before P fragment loads (same warp)

        // --- out += P[16q,64k] @ V[64k,64d] ---
        const uint32_t* Pu = (const uint32_t*)Pw;
        const uint32_t* Vu = (const uint32_t*)Vscur;
        #pragma unroll
        for (int ks = 0; ks < 8; ks++) {
            uint32_t a[4];
            a[0] = Pu[g * AT_STRIDE + ks * 8 + t];
            a[1] = Pu[(g + 8) * AT_STRIDE + ks * 8 + t];
            a[2] = Pu[g * AT_STRIDE + ks * 8 + t + 4];
            a[3] = Pu[(g + 8) * AT_STRIDE + ks * 8 + t + 4];
            #pragma unroll
            for (int dt = 0; dt < 8; dt++) {
                uint32_t bf[2] = { Vu[(ks * 8 + t) * AT_STRIDE + dt * 8 + g],
                                   Vu[(ks * 8 + t + 4) * AT_STRIDE + dt * 8 + g] };
                mma8(acc[dt], a, bf);
            }
        }
    }

    // final: reduce Z over quad lanes, normalize, store
    Zs0 += __shfl_xor_sync(0xffffffffu, Zs0, 1);
    Zs0 += __shfl_xor_sync(0xffffffffu, Zs0, 2);
    Zs1 += __shfl_xor_sync(0xffffffffu, Zs1, 1);
    Zs1 += __shfl_xor_sync(0xffffffffu, Zs1, 2);
    Zm0 += __shfl_xor_sync(0xffffffffu, Zm0, 1);
    Zm0 += __shfl_xor_sync(0xffffffffu, Zm0, 2);
    Zm1 += __shfl_xor_sync(0xffffffffu, Zm1, 1);
    Zm1 += __shfl_xor_sync(0xffffffffu, Zm1, 2);
    float inv0 = 1.0f / (Zm0 + 1e-8f * Zs0);
    float inv1 = 1.0f / (Zm1 + 1e-8f * Zs1);

    #pragma unroll
    for (int dt = 0; dt < 8; dt++) {
        int c = dt * 8 + 2 * t;
        *(float2*)&Obase[(size_t)(qw + g) * D_ + c] =
            make_float2(acc[dt][0] * inv0, acc[dt][1] * inv0);
        *(float2*)&Obase[(size_t)(qw + g + 8) * D_ + c] =
            make_float2(acc[dt][2] * inv1, acc[dt][3] * inv1);
    }
}

// ---------------------------------------------------------------------------
extern "C" void kernel_launch(void* const* d_in, const int* in_sizes, int n_in,
                              void* d_out, int out_size)
{
    const float* gene    = (const float*)d_in[0];
    const float* expr    = (const float*)d_in[1];
    const float* Mm      = (const float*)d_in[2];
    const float* W_fused = (const float*)d_in[3];
    const float* b_fused = (const float*)d_in[4];
    const float* W_Q     = (const float*)d_in[5];
    const float* b_Q     = (const float*)d_in[6];
    const float* W_K     = (const float*)d_in[7];
    const float* b_K     = (const float*)d_in[8];
    const float* W_V     = (const float*)d_in[9];
    const float* b_V     = (const float*)d_in[10];
    const float* W_O     = (const float*)d_in[11];
    const float* b_O     = (const float*)d_in[12];
    float* out = (float*)d_out;

    float *fusedp, *Qp, *Kp, *Vp, *attp;
    cudaGetSymbolAddress((void**)&fusedp, g_fused);
    cudaGetSymbolAddress((void**)&Qp, g_Q);
    cudaGetSymbolAddress((void**)&Kp, g_K);
    cudaGetSymbolAddress((void**)&Vp, g_V);
    cudaGetSymbolAddress((void**)&attp, g_att);

    cudaFuncSetAttribute(attn_tf32,
                         cudaFuncAttributeMaxDynamicSharedMemorySize, ATTN_SMEM);

    dim3 gg(D_ / 128, NR / 128);   // (4, 64)

    gemm_tf32<<<gg, 256>>>(gene, expr, 512, W_fused, b_fused, fusedp, 1024, 0);
    gemm_tf32<<<gg, 256>>>(fusedp, fusedp, 512, W_Q, b_Q, Qp, 512, 1);
    gemm_tf32<<<gg, 256>>>(fusedp, fusedp, 512, W_K, b_K, Kp, 512, 1);
    gemm_tf32<<<gg, 256>>>(expr,   expr,   512, W_V, b_V, Vp, 512, 1);
    attn_tf32<<<dim3(S_ / 128, H_, B_), 256, ATTN_SMEM>>>(Qp, Kp, Vp, Mm, attp);
    gemm_tf32<<<gg, 256>>>(attp, attp, 512, W_O, b_O, out, 512, 0);
}

// round 15
// speedup vs baseline: 1.5091x; 1.0218x over previous
#include <cuda_runtime.h>
#include <math.h>
#include <stdint.h>

#define B_  4
#define S_  2048
#define D_  512
#define H_  8
#define HD_ 64
#define NR  (B_ * S_)   // 8192 rows

// Scratch buffers (no allocation allowed in kernel_launch).
__device__ __align__(16) float g_fused[NR * D_];
__device__ __align__(16) float g_Q[NR * D_];
__device__ __align__(16) float g_K[NR * D_];
__device__ __align__(16) float g_V[NR * D_];
__device__ __align__(16) float g_att[NR * D_];

// ---------------------------------------------------------------------------
// TF32 / cp.async / math helpers
// ---------------------------------------------------------------------------
__device__ __forceinline__ uint32_t f2tf(float x) {
    uint32_t u;
    asm("cvt.rna.tf32.f32 %0, %1;" : "=r"(u) : "f"(x));
    return u;
}
__device__ __forceinline__ float f2tff(float x) {
    return __uint_as_float(f2tf(x));
}
// Fast exp2 via MUFU.EX2 (single-instruction approx; rel err ~2^-21).
__device__ __forceinline__ float ex2(float x) {
    float r;
    asm("ex2.approx.ftz.f32 %0, %1;" : "=f"(r) : "f"(x));
    return r;
}
// D(16x8,f32) += A(16x8,tf32,row) * B(8x8,tf32,col)
__device__ __forceinline__ void mma8(float* d, const uint32_t* a, const uint32_t* b) {
    asm volatile(
        "mma.sync.aligned.m16n8k8.row.col.f32.tf32.tf32.f32 "
        "{%0,%1,%2,%3}, {%4,%5,%6,%7}, {%8,%9}, {%0,%1,%2,%3};"
        : "+f"(d[0]), "+f"(d[1]), "+f"(d[2]), "+f"(d[3])
        : "r"(a[0]), "r"(a[1]), "r"(a[2]), "r"(a[3]), "r"(b[0]), "r"(b[1]));
}
__device__ __forceinline__ void cp16(void* smem_dst, const void* gsrc) {
    uint32_t s = (uint32_t)__cvta_generic_to_shared(smem_dst);
    asm volatile("cp.async.cg.shared.global [%0], [%1], 16;" :: "r"(s), "l"(gsrc));
}
#define CP_COMMIT() asm volatile("cp.async.commit_group;")
#define CP_WAIT(n)  asm volatile("cp.async.wait_group %0;" :: "n"(n))

// ---------------------------------------------------------------------------
// TF32 tensor-core GEMM core: C[M,512] = A[M,K] @ Bw[K,512] + bias.
// Double-buffered smem: one __syncthreads per k-iter, LDG prefetch overlaps
// mma. round_out=1: store outputs pre-rounded to tf32 (cvt.rna; idempotent
// for consumers that would re-round on load).
// Concat: logical A row = A[0..KA) ++ A2[0..K-KA); k-tiles never straddle KA.
// CTA 128x128, 256 threads, 8 warps (2m x 4n), warp tile 64x32.
// ---------------------------------------------------------------------------
__device__ __forceinline__ void gemm_core(
    const float* __restrict__ A, const float* __restrict__ A2, int KA,
    const float* __restrict__ Bw, const float* __restrict__ bias,
    float* __restrict__ C, int K, int round_out,
    int bx, int by)
{
    __shared__ float As[2][128][20];   // [m][k], pad: frag LDS conflict-free
    __shared__ float Bs[2][16][132];   // [k][n]

    const int tid  = threadIdx.x;
    const int lane = tid & 31, wid = tid >> 5;
    const int g = lane >> 2, t = lane & 3;
    const int wm = (wid >> 2) * 64;
    const int wn = (wid & 3) * 32;
    const int row0 = by * 128;
    const int col0 = bx * 128;

    const int ar = tid >> 1;            // 0..127
    const int ac = (tid & 1) * 8;       // 0 or 8
    const int bk = tid >> 4;            // 0..15
    const int bc = (tid & 15) * 8;      // 0..120

    float acc[4][4][4];
    #pragma unroll
    for (int i = 0; i < 4; i++)
        #pragma unroll
        for (int j = 0; j < 4; j++)
            #pragma unroll
            for (int v = 0; v < 4; v++) acc[i][j][v] = 0.0f;

    const int niter = K >> 4;
    float4 pa0, pa1, pb0, pb1;

    auto prefetch = [&](int it) {
        int k0 = it << 4;
        const float* src = (k0 < KA) ? A : A2;
        int koff = (k0 < KA) ? k0 : k0 - KA;
        const float* p = &src[(size_t)(row0 + ar) * KA + koff + ac];
        pa0 = *(const float4*)p; pa1 = *(const float4*)(p + 4);
        const float* q = &Bw[(size_t)(k0 + bk) * D_ + col0 + bc];
        pb0 = *(const float4*)q; pb1 = *(const float4*)(q + 4);
    };
    auto stage = [&](int buf) {
        *(float4*)&As[buf][ar][ac]     = make_float4(f2tff(pa0.x), f2tff(pa0.y), f2tff(pa0.z), f2tff(pa0.w));
        *(float4*)&As[buf][ar][ac + 4] = make_float4(f2tff(pa1.x), f2tff(pa1.y), f2tff(pa1.z), f2tff(pa1.w));
        *(float4*)&Bs[buf][bk][bc]     = make_float4(f2tff(pb0.x), f2tff(pb0.y), f2tff(pb0.z), f2tff(pb0.w));
        *(float4*)&Bs[buf][bk][bc + 4] = make_float4(f2tff(pb1.x), f2tff(pb1.y), f2tff(pb1.z), f2tff(pb1.w));
    };

    prefetch(0);
    stage(0);
    __syncthreads();

    for (int it = 0; it < niter; it++) {
        const int cur = it & 1;
        if (it + 1 < niter) prefetch(it + 1);

        const uint32_t* Au = (const uint32_t*)As[cur];
        const uint32_t* Bu = (const uint32_t*)Bs[cur];
        #pragma unroll
        for (int ks = 0; ks < 2; ks++) {
            const int kk = ks * 8;
            uint32_t a[4][4];
            #pragma unroll
            for (int mt = 0; mt < 4; mt++) {
                int m = wm + mt * 16;
                a[mt][0] = Au[(m + g) * 20 + kk + t];
                a[mt][1] = Au[(m + g + 8) * 20 + kk + t];
                a[mt][2] = Au[(m + g) * 20 + kk + t + 4];
                a[mt][3] = Au[(m + g + 8) * 20 + kk + t + 4];
            }
            #pragma unroll
            for (int nt = 0; nt < 4; nt++) {
                int n = wn + nt * 8 + g;
                uint32_t bf[2] = { Bu[(kk + t) * 132 + n], Bu[(kk + t + 4) * 132 + n] };
                #pragma unroll
                for (int mt = 0; mt < 4; mt++) mma8(acc[mt][nt], a[mt], bf);
            }
        }

        if (it + 1 < niter) {
            stage(cur ^ 1);
            __syncthreads();
        }
    }

    // epilogue: bias + store (c0,c1 adjacent cols -> float2)
    #pragma unroll
    for (int mt = 0; mt < 4; mt++) {
        int r = row0 + wm + mt * 16 + g;
        #pragma unroll
        for (int nt = 0; nt < 4; nt++) {
            int c = col0 + wn + nt * 8 + 2 * t;
            float b0v = bias[c], b1v = bias[c + 1];
            float o0 = acc[mt][nt][0] + b0v, o1 = acc[mt][nt][1] + b1v;
            float o2 = acc[mt][nt][2] + b0v, o3 = acc[mt][nt][3] + b1v;
            if (round_out) {
                o0 = f2tff(o0); o1 = f2tff(o1); o2 = f2tff(o2); o3 = f2tff(o3);
            }
            *(float2*)&C[(size_t)r * D_ + c]       = make_float2(o0, o1);
            *(float2*)&C[(size_t)(r + 8) * D_ + c] = make_float2(o2, o3);
        }
    }
}

__global__ __launch_bounds__(256, 2) void gemm_tf32(
    const float* __restrict__ A, const float* __restrict__ A2, int KA,
    const float* __restrict__ Bw, const float* __restrict__ bias,
    float* __restrict__ C, int K, int round_out)
{
    gemm_core(A, A2, KA, Bw, bias, C, K, round_out, blockIdx.x, blockIdx.y);
}

// Merged Q/K/V projection: one launch, gridDim.z selects the problem.
// z=0: Q = fused @ W_Q + b_Q;  z=1: K = fused @ W_K + b_K;
// z=2: V = expr @ W_V + b_V.  All K=512, outputs pre-rounded to tf32.
__global__ __launch_bounds__(256, 2) void gemm_qkv(
    const float* __restrict__ fused, const float* __restrict__ expr,
    const float* __restrict__ WQ, const float* __restrict__ bQ, float* __restrict__ Q,
    const float* __restrict__ WK, const float* __restrict__ bK, float* __restrict__ K_,
    const float* __restrict__ WV, const float* __restrict__ bV, float* __restrict__ V)
{
    const int z = blockIdx.z;
    const float* A  = (z == 2) ? expr : fused;
    const float* Bw = (z == 0) ? WQ : (z == 1) ? WK : WV;
    const float* bs = (z == 0) ? bQ : (z == 1) ? bK : bV;
    float*       C  = (z == 0) ? Q  : (z == 1) ? K_ : V;
    gemm_core(A, A, 512, Bw, bs, C, 512, 1, blockIdx.x, blockIdx.y);
}

// ---------------------------------------------------------------------------
// TF32 fused masked-softmax attention (flash-style, NO online max).
// Scores are bounded (unit-variance Q/K, HD=64, scale .125, M in [0,1]) so
// exp2 cannot overflow, and a max-shift cancels exactly in
//   A_bar = p*M / (Zm + EPS*Zs),  p = exp2(CL*M*(Q.K)),  Zs=sum p, Zm=sum p*M.
// CTA: 128 q rows, 256 threads (8 warps x 16q). 32 key blocks of 64.
// Q/K/V arrive PRE-ROUNDED to tf32 (producer GEMM round_out=1), so all tile
// movement is raw cp.async gmem->smem: zero staging registers. Q fragments
// live in registers; P scratch aliases the dead Q smem region (warp-private
// rows). K/V double-buffered: next tile's cp.async issues after this iter's
// sync, overlapping the softmax+PV phases. One __syncthreads per iteration.
// M is read directly from gmem (L2-resident) in the C-fragment pattern.
// exp2 is MUFU.EX2 via inline PTX (ex2.approx.ftz).
// ---------------------------------------------------------------------------
#define AT_STRIDE 68
#define ATTN_SMEM ((128 * AT_STRIDE + 4 * 64 * AT_STRIDE) * 4)   // 104448 B

__global__ __launch_bounds__(256, 2) void attn_tf32(
    const float* __restrict__ Qg, const float* __restrict__ Kg,
    const float* __restrict__ Vg, const float* __restrict__ Mg,
    float* __restrict__ Og)
{
    extern __shared__ float sm[];
    float* Qs = sm;                            // [128][68] (q x d) -> later P scratch
    float* Ks = sm + 128 * AT_STRIDE;          // [2][64][68] (k x d)
    float* Vs = Ks + 2 * 64 * AT_STRIDE;       // [2][64][68] (k x d)
    float* Ps = sm;                            // aliases Qs (per-warp 16 rows)

    const int tid  = threadIdx.x;
    const int lane = tid & 31, w = tid >> 5;
    const int g = lane >> 2, t = lane & 3;
    const int qw = w * 16;
    const int b = blockIdx.z, h = blockIdx.y, qb = blockIdx.x;

    const float CL = 0.125f * 1.4426950408889634f;   // scale * log2e

    const float* Qbase = Qg + ((size_t)(b * S_ + qb * 128)) * D_ + h * HD_;
    const float* Kbase = Kg + ((size_t)(b * S_)) * D_ + h * HD_;
    const float* Vbase = Vg + ((size_t)(b * S_)) * D_ + h * HD_;
    const float* Mrow0 = Mg + (size_t)b * S_ * S_ + (size_t)(qb * 128 + qw + g) * S_;
    const float* Mrow1 = Mrow0 + (size_t)8 * S_;
    float*       Obase = Og + ((size_t)(b * S_ + qb * 128)) * D_ + h * HD_;

    const int ldr = tid >> 4;              // cooperative-load row base (0..15)
    const int ldc = (tid & 15) * 4;        // cooperative-load col

    // ---- prologue: cp.async Q (group A), then K/V tile 0 (group B) ----
    #pragma unroll
    for (int itl = 0; itl < 8; itl++) {
        int r = ldr + itl * 16;
        cp16(&Qs[r * AT_STRIDE + ldc], &Qbase[(size_t)r * D_ + ldc]);
    }
    CP_COMMIT();
    #pragma unroll
    for (int itl = 0; itl < 4; itl++) {
        int r = ldr + itl * 16;
        cp16(&Ks[r * AT_STRIDE + ldc], &Kbase[(size_t)r * D_ + ldc]);
        cp16(&Vs[r * AT_STRIDE + ldc], &Vbase[(size_t)r * D_ + ldc]);
    }
    CP_COMMIT();

    CP_WAIT(1);          // Q arrived (K/V tile 0 may still be in flight)
    __syncthreads();

    // ---- Q fragments -> registers (loop-invariant) ----
    uint32_t qa[8][4];
    {
        const uint32_t* Qu = (const uint32_t*)Qs;
        #pragma unroll
        for (int ks = 0; ks < 8; ks++) {
            qa[ks][0] = Qu[(qw + g) * AT_STRIDE + ks * 8 + t];
            qa[ks][1] = Qu[(qw + g + 8) * AT_STRIDE + ks * 8 + t];
            qa[ks][2] = Qu[(qw + g) * AT_STRIDE + ks * 8 + t + 4];
            qa[ks][3] = Qu[(qw + g + 8) * AT_STRIDE + ks * 8 + t + 4];
        }
    }

    float acc[8][4];
    #pragma unroll
    for (int i = 0; i < 8; i++)
        #pragma unroll
        for (int v = 0; v < 4; v++) acc[i][v] = 0.0f;
    float Zs0 = 0.f, Zs1 = 0.f, Zm0 = 0.f, Zm1 = 0.f;

    for (int kb = 0; kb < S_ / 64; kb++) {
        const int cur = kb & 1;
        const bool has_next = (kb + 1 < S_ / 64);
        const float* Kscur = Ks + cur * 64 * AT_STRIDE;
        const float* Vscur = Vs + cur * 64 * AT_STRIDE;

        CP_WAIT(0);        // tile kb fully arrived
        __syncthreads();   // all warps see it; buf^1 reads from iter kb-1 done

        // --- scores: S[16q,64k] = Q @ K^T (warp) ---
        const uint32_t* Ku = (const uint32_t*)Kscur;
        float sc[8][4];
        #pragma unroll
        for (int nt = 0; nt < 8; nt++)
            #pragma unroll
            for (int v = 0; v < 4; v++) sc[nt][v] = 0.0f;

        #pragma unroll
        for (int ks = 0; ks < 8; ks++) {
            #pragma unroll
            for (int nt = 0; nt < 8; nt++) {
                uint32_t bf[2] = { Ku[(nt * 8 + g) * AT_STRIDE + ks * 8 + t],
                                   Ku[(nt * 8 + g) * AT_STRIDE + ks * 8 + t + 4] };
                mma8(sc[nt], qa[ks], bf);
            }
        }

        // --- issue cp.async for tile kb+1 into the other buffer ---
        // Safe: every thread passed this iter's __syncthreads, so no thread
        // still reads buf^1 (last read at iter kb-1). Copy overlaps softmax+PV.
        if (has_next) {
            float* Ksn = Ks + (cur ^ 1) * 64 * AT_STRIDE;
            float* Vsn = Vs + (cur ^ 1) * 64 * AT_STRIDE;
            #pragma unroll
            for (int itl = 0; itl < 4; itl++) {
                int r = ldr + itl * 16;
                cp16(&Ksn[r * AT_STRIDE + ldc],
                     &Kbase[(size_t)((kb + 1) * 64 + r) * D_ + ldc]);
                cp16(&Vsn[r * AT_STRIDE + ldc],
                     &Vbase[(size_t)((kb + 1) * 64 + r) * D_ + ldc]);
            }
            CP_COMMIT();
        }

        // --- single pass: mask*scale, exp2, Z sums, P (= p*M) to smem tf32 ---
        const float* Mc0 = Mrow0 + kb * 64;
        const float* Mc1 = Mrow1 + kb * 64;
        float* Pw = Ps + w * 16 * AT_STRIDE;
        #pragma unroll
        for (int nt = 0; nt < 8; nt++) {
            float2 mA = *(const float2*)&Mc0[nt * 8 + 2 * t];
            float2 mB = *(const float2*)&Mc1[nt * 8 + 2 * t];
            float p0 = ex2(sc[nt][0] * (CL * mA.x));
            float p1 = ex2(sc[nt][1] * (CL * mA.y));
            float p2 = ex2(sc[nt][2] * (CL * mB.x));
            float p3 = ex2(sc[nt][3] * (CL * mB.y));
            Zs0 += p0 + p1; Zs1 += p2 + p3;
            p0 *= mA.x; p1 *= mA.y; p2 *= mB.x; p3 *= mB.y;
            Zm0 += p0 + p1; Zm1 += p2 + p3;
            *(float2*)&Pw[g * AT_STRIDE + nt * 8 + 2 * t] =
                make_float2(f2tff(p0), f2tff(p1));
            *(float2*)&Pw[(g + 8) * AT_STRIDE + nt * 8 + 2 * t] =
                make_float2(f2tff(p2), f2tff(p3));
        }
        __syncwarp();   // order P stores before P fragment loads (same warp)

        // --- out += P[16q,64k] @ V[64k,64d] ---
        const uint32_t* Pu = (const uint32_t*)Pw;
        const uint32_t* Vu = (const uint32_t*)Vscur;
        #pragma unroll
        for (int ks = 0; ks < 8; ks++) {
            uint32_t a[4];
            a[0] = Pu[g * AT_STRIDE + ks * 8 + t];
            a[1] = Pu[(g + 8) * AT_STRIDE + ks * 8 + t];
            a[2] = Pu[g * AT_STRIDE + ks * 8 + t + 4];
            a[3] = Pu[(g + 8) * AT_STRIDE + ks * 8 + t + 4];
            #pragma unroll
            for (int dt = 0; dt < 8; dt++) {
                uint32_t bf[2] = { Vu[(ks * 8 + t) * AT_STRIDE + dt * 8 + g],
                                   Vu[(ks * 8 + t + 4) * AT_STRIDE + dt * 8 + g] };
                mma8(acc[dt], a, bf);
            }
        }
    }

    // final: reduce Z over quad lanes, normalize, store
    Zs0 += __shfl_xor_sync(0xffffffffu, Zs0, 1);
    Zs0 += __shfl_xor_sync(0xffffffffu, Zs0, 2);
    Zs1 += __shfl_xor_sync(0xffffffffu, Zs1, 1);
    Zs1 += __shfl_xor_sync(0xffffffffu, Zs1, 2);
    Zm0 += __shfl_xor_sync(0xffffffffu, Zm0, 1);
    Zm0 += __shfl_xor_sync(0xffffffffu, Zm0, 2);
    Zm1 += __shfl_xor_sync(0xffffffffu, Zm1, 1);
    Zm1 += __shfl_xor_sync(0xffffffffu, Zm1, 2);
    float inv0 = 1.0f / (Zm0 + 1e-8f * Zs0);
    float inv1 = 1.0f / (Zm1 + 1e-8f * Zs1);

    #pragma unroll
    for (int dt = 0; dt < 8; dt++) {
        int c = dt * 8 + 2 * t;
        *(float2*)&Obase[(size_t)(qw + g) * D_ + c] =
            make_float2(acc[dt][0] * inv0, acc[dt][1] * inv0);
        *(float2*)&Obase[(size_t)(qw + g + 8) * D_ + c] =
            make_float2(acc[dt][2] * inv1, acc[dt][3] * inv1);
    }
}

// ---------------------------------------------------------------------------
extern "C" void kernel_launch(void* const* d_in, const int* in_sizes, int n_in,
                              void* d_out, int out_size)
{
    const float* gene    = (const float*)d_in[0];
    const float* expr    = (const float*)d_in[1];
    const float* Mm      = (const float*)d_in[2];
    const float* W_fused = (const float*)d_in[3];
    const float* b_fused = (const float*)d_in[4];
    const float* W_Q     = (const float*)d_in[5];
    const float* b_Q     = (const float*)d_in[6];
    const float* W_K     = (const float*)d_in[7];
    const float* b_K     = (const float*)d_in[8];
    const float* W_V     = (const float*)d_in[9];
    const float* b_V     = (const float*)d_in[10];
    const float* W_O     = (const float*)d_in[11];
    const float* b_O     = (const float*)d_in[12];
    float* out = (float*)d_out;

    float *fusedp, *Qp, *Kp, *Vp, *attp;
    cudaGetSymbolAddress((void**)&fusedp, g_fused);
    cudaGetSymbolAddress((void**)&Qp, g_Q);
    cudaGetSymbolAddress((void**)&Kp, g_K);
    cudaGetSymbolAddress((void**)&Vp, g_V);
    cudaGetSymbolAddress((void**)&attp, g_att);

    cudaFuncSetAttribute(attn_tf32,
                         cudaFuncAttributeMaxDynamicSharedMemorySize, ATTN_SMEM);

    dim3 gg(D_ / 128, NR / 128);        // (4, 64)
    dim3 gqkv(D_ / 128, NR / 128, 3);   // (4, 64, 3)

    gemm_tf32<<<gg, 256>>>(gene, expr, 512, W_fused, b_fused, fusedp, 1024, 0);
    gemm_qkv<<<gqkv, 256>>>(fusedp, expr,
                            W_Q, b_Q, Qp,
                            W_K, b_K, Kp,
                            W_V, b_V, Vp);
    attn_tf32<<<dim3(S_ / 128, H_, B_), 256, ATTN_SMEM>>>(Qp, Kp, Vp, Mm, attp);
    gemm_tf32<<<gg, 256>>>(attp, attp, 512, W_O, b_O, out, 512, 0);
}